// round 2
// baseline (speedup 1.0000x reference)
#include <cuda_runtime.h>

// Problem constants (fixed by setup_inputs)
#define B_  8
#define C_  24
#define H_  320
#define W_  640
#define HW_ (H_ * W_)            // 204800
#define PLANE4_ (HW_ / 4)        // 51200 float4 groups per image plane
#define NPIX4_ (B_ * PLANE4_)    // 409600 total float4 groups
#define NBHW_ (B_ * HW_)         // pred element count / prob plane base

__global__ __launch_bounds__(256)
void sparse_regression_stream_kernel(const float* __restrict__ cost,
                                     const float* __restrict__ disp,
                                     float* __restrict__ out)
{
    int p = blockIdx.x * blockDim.x + threadIdx.x;
    if (p >= NPIX4_) return;

    int b = p / PLANE4_;
    int r = p - b * PLANE4_;                 // float4 index within plane
    long base = (long)b * C_ * HW_ + (long)r * 4;

    const float4* cbase = reinterpret_cast<const float4*>(cost + base);
    const float4* dbase = reinterpret_cast<const float4*>(disp + base);

    // running top-2 (value, disparity) per lane — no indices needed
    float v0[4], v1[4], d0[4], d1[4];

    // c = 0
    {
        float4 cx = cbase[0];
        float4 dx = dbase[0];
        float cv[4] = {cx.x, cx.y, cx.z, cx.w};
        float dv[4] = {dx.x, dx.y, dx.z, dx.w};
        #pragma unroll
        for (int l = 0; l < 4; ++l) {
            v0[l] = cv[l]; d0[l] = dv[l];
            v1[l] = -3.4e38f; d1[l] = 0.0f;
        }
    }
    // c = 1
    {
        float4 cx = cbase[PLANE4_];
        float4 dx = dbase[PLANE4_];
        float cv[4] = {cx.x, cx.y, cx.z, cx.w};
        float dv[4] = {dx.x, dx.y, dx.z, dx.w};
        #pragma unroll
        for (int l = 0; l < 4; ++l) {
            if (cv[l] > v0[l]) {
                v1[l] = v0[l]; d1[l] = d0[l];
                v0[l] = cv[l]; d0[l] = dv[l];
            } else {
                v1[l] = cv[l]; d1[l] = dv[l];
            }
        }
    }

    #pragma unroll
    for (int c = 2; c < C_; ++c) {
        float4 cx = cbase[(long)c * PLANE4_];
        float4 dx = dbase[(long)c * PLANE4_];
        float cv[4] = {cx.x, cx.y, cx.z, cx.w};
        float dv[4] = {dx.x, dx.y, dx.z, dx.w};
        #pragma unroll
        for (int l = 0; l < 4; ++l) {
            float v = cv[l];
            float d = dv[l];
            if (v > v0[l]) {
                v1[l] = v0[l]; d1[l] = d0[l];
                v0[l] = v;     d0[l] = d;
            } else if (v > v1[l]) {
                v1[l] = v;     d1[l] = d;
            }
        }
    }

    // 2-way softmax (v1 <= v0, so e in (0,1]) and weighted disparity
    float pred[4], pr0[4], pr1[4];
    #pragma unroll
    for (int l = 0; l < 4; ++l) {
        float e   = __expf(v1[l] - v0[l]);
        float inv = 1.0f / (1.0f + e);
        float p0  = inv;
        float p1  = e * inv;
        pr0[l] = p0;
        pr1[l] = p1;
        pred[l] = d0[l] * p0 + d1[l] * p1;
    }

    long po = (long)b * HW_ + (long)r * 4;
    *reinterpret_cast<float4*>(out + po) = make_float4(pred[0], pred[1], pred[2], pred[3]);

    // prob [B, 2, H, W] after pred [B, H, W]
    long q0 = (long)NBHW_ + ((long)b * 2 + 0) * HW_ + (long)r * 4;
    long q1 = (long)NBHW_ + ((long)b * 2 + 1) * HW_ + (long)r * 4;
    *reinterpret_cast<float4*>(out + q0) = make_float4(pr0[0], pr0[1], pr0[2], pr0[3]);
    *reinterpret_cast<float4*>(out + q1) = make_float4(pr1[0], pr1[1], pr1[2], pr1[3]);
}

extern "C" void kernel_launch(void* const* d_in, const int* in_sizes, int n_in,
                              void* d_out, int out_size)
{
    const float* cost = (const float*)d_in[0];
    const float* disp = (const float*)d_in[1];
    float* out = (float*)d_out;

    const int threads = 256;
    const int blocks = (NPIX4_ + threads - 1) / threads;
    sparse_regression_stream_kernel<<<blocks, threads>>>(cost, disp, out);
}

// round 3
// speedup vs baseline: 1.2326x; 1.2326x over previous
#include <cuda_runtime.h>

// Problem constants (fixed by setup_inputs)
#define B_  8
#define C_  24
#define H_  320
#define W_  640
#define HW_ (H_ * W_)            // 204800
#define PLANE4_ (HW_ / 4)        // 51200 float4 groups per image plane
#define NPIX4_ (B_ * PLANE4_)    // 409600 total float4 groups
#define NBHW_ (B_ * HW_)         // pred element count / prob plane base

#define CHUNK_ 6                 // channels per load batch (24 = 4 * 6)

__global__ __launch_bounds__(256)
void sparse_regression_mlp_kernel(const float* __restrict__ cost,
                                  const float* __restrict__ disp,
                                  float* __restrict__ out)
{
    int p = blockIdx.x * blockDim.x + threadIdx.x;
    if (p >= NPIX4_) return;

    int b = p / PLANE4_;
    int r = p - b * PLANE4_;                 // float4 index within plane
    long base = (long)b * C_ * HW_ + (long)r * 4;

    const float4* cbase = reinterpret_cast<const float4*>(cost + base);
    const float4* dbase = reinterpret_cast<const float4*>(disp + base);

    // running top-2 (value, disparity) per lane
    float v0[4], v1[4], d0[4], d1[4];
    #pragma unroll
    for (int l = 0; l < 4; ++l) {
        v0[l] = -3.4e38f; d0[l] = 0.0f;
        v1[l] = -3.4e38f; d1[l] = 0.0f;
    }

    for (int ch = 0; ch < C_; ch += CHUNK_) {
        // ---- batched loads: all 12 LDG.128 issued before any consume ----
        float4 creg[CHUNK_], dreg[CHUNK_];
        #pragma unroll
        for (int j = 0; j < CHUNK_; ++j) {
            long off = (long)(ch + j) * PLANE4_;
            creg[j] = __ldcs(cbase + off);
            dreg[j] = __ldcs(dbase + off);
        }
        // ---- consume ----
        #pragma unroll
        for (int j = 0; j < CHUNK_; ++j) {
            float cv[4] = {creg[j].x, creg[j].y, creg[j].z, creg[j].w};
            float dv[4] = {dreg[j].x, dreg[j].y, dreg[j].z, dreg[j].w};
            #pragma unroll
            for (int l = 0; l < 4; ++l) {
                float v = cv[l];
                float d = dv[l];
                if (v > v0[l]) {
                    v1[l] = v0[l]; d1[l] = d0[l];
                    v0[l] = v;     d0[l] = d;
                } else if (v > v1[l]) {
                    v1[l] = v;     d1[l] = d;
                }
            }
        }
    }

    // 2-way softmax (v1 <= v0, so e in (0,1]) and weighted disparity
    float pred[4], pr0[4], pr1[4];
    #pragma unroll
    for (int l = 0; l < 4; ++l) {
        float e   = __expf(v1[l] - v0[l]);
        float inv = 1.0f / (1.0f + e);
        float p0  = inv;
        float p1  = e * inv;
        pr0[l] = p0;
        pr1[l] = p1;
        pred[l] = d0[l] * p0 + d1[l] * p1;
    }

    long po = (long)b * HW_ + (long)r * 4;
    *reinterpret_cast<float4*>(out + po) = make_float4(pred[0], pred[1], pred[2], pred[3]);

    // prob [B, 2, H, W] after pred [B, H, W]
    long q0 = (long)NBHW_ + ((long)b * 2 + 0) * HW_ + (long)r * 4;
    long q1 = (long)NBHW_ + ((long)b * 2 + 1) * HW_ + (long)r * 4;
    *reinterpret_cast<float4*>(out + q0) = make_float4(pr0[0], pr0[1], pr0[2], pr0[3]);
    *reinterpret_cast<float4*>(out + q1) = make_float4(pr1[0], pr1[1], pr1[2], pr1[3]);
}

extern "C" void kernel_launch(void* const* d_in, const int* in_sizes, int n_in,
                              void* d_out, int out_size)
{
    const float* cost = (const float*)d_in[0];
    const float* disp = (const float*)d_in[1];
    float* out = (float*)d_out;

    const int threads = 256;
    const int blocks = (NPIX4_ + threads - 1) / threads;
    sparse_regression_mlp_kernel<<<blocks, threads>>>(cost, disp, out);
}

// round 4
// speedup vs baseline: 1.2348x; 1.0018x over previous
#include <cuda_runtime.h>

// Problem constants (fixed by setup_inputs)
#define B_  8
#define C_  24
#define H_  320
#define W_  640
#define HW_ (H_ * W_)            // 204800
#define PLANE4_ (HW_ / 4)        // 51200 float4 groups per image plane
#define NPIX4_ (B_ * PLANE4_)    // 409600 total float4 groups
#define NBHW_ (B_ * HW_)         // pred element count / prob plane base

#define CHUNK_ 6                 // channels per load batch (24 = 4 * 6)

__global__ __launch_bounds__(256)
void sparse_regression_mlp_kernel(const float* __restrict__ cost,
                                  const float* __restrict__ disp,
                                  float* __restrict__ out)
{
    int p = blockIdx.x * blockDim.x + threadIdx.x;
    if (p >= NPIX4_) return;

    int b = p / PLANE4_;
    int r = p - b * PLANE4_;                 // float4 index within plane
    long base = (long)b * C_ * HW_ + (long)r * 4;

    const float4* cbase = reinterpret_cast<const float4*>(cost + base);
    const float4* dbase = reinterpret_cast<const float4*>(disp + base);

    // running top-2 (value, disparity) per lane
    float v0[4], v1[4], d0[4], d1[4];
    #pragma unroll
    for (int l = 0; l < 4; ++l) {
        v0[l] = -3.4e38f; d0[l] = 0.0f;
        v1[l] = -3.4e38f; d1[l] = 0.0f;
    }

    for (int ch = 0; ch < C_; ch += CHUNK_) {
        // ---- batched loads: all 12 LDG.128 issued before any consume ----
        float4 creg[CHUNK_], dreg[CHUNK_];
        #pragma unroll
        for (int j = 0; j < CHUNK_; ++j) {
            long off = (long)(ch + j) * PLANE4_;
            creg[j] = __ldcs(cbase + off);
            dreg[j] = __ldcs(dbase + off);
        }
        // ---- consume ----
        #pragma unroll
        for (int j = 0; j < CHUNK_; ++j) {
            float cv[4] = {creg[j].x, creg[j].y, creg[j].z, creg[j].w};
            float dv[4] = {dreg[j].x, dreg[j].y, dreg[j].z, dreg[j].w};
            #pragma unroll
            for (int l = 0; l < 4; ++l) {
                float v = cv[l];
                float d = dv[l];
                if (v > v0[l]) {
                    v1[l] = v0[l]; d1[l] = d0[l];
                    v0[l] = v;     d0[l] = d;
                } else if (v > v1[l]) {
                    v1[l] = v;     d1[l] = d;
                }
            }
        }
    }

    // 2-way softmax (v1 <= v0, so e in (0,1]) and weighted disparity
    float pred[4], pr0[4], pr1[4];
    #pragma unroll
    for (int l = 0; l < 4; ++l) {
        float e   = __expf(v1[l] - v0[l]);
        float inv = 1.0f / (1.0f + e);
        float p0  = inv;
        float p1  = e * inv;
        pr0[l] = p0;
        pr1[l] = p1;
        pred[l] = d0[l] * p0 + d1[l] * p1;
    }

    long po = (long)b * HW_ + (long)r * 4;
    *reinterpret_cast<float4*>(out + po) = make_float4(pred[0], pred[1], pred[2], pred[3]);

    // prob [B, 2, H, W] after pred [B, H, W]
    long q0 = (long)NBHW_ + ((long)b * 2 + 0) * HW_ + (long)r * 4;
    long q1 = (long)NBHW_ + ((long)b * 2 + 1) * HW_ + (long)r * 4;
    *reinterpret_cast<float4*>(out + q0) = make_float4(pr0[0], pr0[1], pr0[2], pr0[3]);
    *reinterpret_cast<float4*>(out + q1) = make_float4(pr1[0], pr1[1], pr1[2], pr1[3]);
}

extern "C" void kernel_launch(void* const* d_in, const int* in_sizes, int n_in,
                              void* d_out, int out_size)
{
    const float* cost = (const float*)d_in[0];
    const float* disp = (const float*)d_in[1];
    float* out = (float*)d_out;

    const int threads = 256;
    const int blocks = (NPIX4_ + threads - 1) / threads;
    sparse_regression_mlp_kernel<<<blocks, threads>>>(cost, disp, out);
}